// round 15
// baseline (speedup 1.0000x reference)
#include <cuda_runtime.h>
#include <cuda_bf16.h>
#include <math.h>
#include <stdint.h>

#define R_DIM 512
#define S_DIM 256
#define D_DIM 256
#define NROWS (R_DIM * S_DIM)        // 131072

// ---------------- scratch (static device arrays; no cudaMalloc) ------------
__device__ float         g_Mn[NROWS * D_DIM];             // layernormed M (fp32)
__device__ __nv_bfloat16 g_QKVG[(size_t)NROWS * 1024];    // q|k|v|gate (bf16)
__device__ __nv_bfloat16 g_O[NROWS * D_DIM];              // gated attn out (bf16)

// q scale: C^-0.5 * log2(e) — attention uses exp2
#define Q_SCALE_LOG2E 0.2550348658f

// ---------------------------------------------------------------------------
// mma.sync + cp.async helpers (base PTX target)
// ---------------------------------------------------------------------------
__device__ __forceinline__ void mma16n8k8(float* d, const uint32_t* a, const uint32_t* b) {
    asm volatile("mma.sync.aligned.m16n8k8.row.col.f32.tf32.tf32.f32 "
        "{%0,%1,%2,%3}, {%4,%5,%6,%7}, {%8,%9}, {%0,%1,%2,%3};"
        : "+f"(d[0]), "+f"(d[1]), "+f"(d[2]), "+f"(d[3])
        : "r"(a[0]), "r"(a[1]), "r"(a[2]), "r"(a[3]), "r"(b[0]), "r"(b[1]));
}

__device__ __forceinline__ void cp16(const float* smem_dst, const float* gsrc) {
    uint32_t d = (uint32_t)__cvta_generic_to_shared(smem_dst);
    asm volatile("cp.async.cg.shared.global [%0], [%1], 16;" :: "r"(d), "l"(gsrc));
}

__device__ __forceinline__ float ex2_approx(float x) {
    float y;
    asm("ex2.approx.ftz.f32 %0, %1;" : "=f"(y) : "f"(x));
    return y;
}

// 8 bf16 (one uint4) -> 8 floats
__device__ __forceinline__ void bf8_to_f8(uint4 v, float* f) {
    float2 t;
    t = __bfloat1622float2(*(__nv_bfloat162*)&v.x); f[0] = t.x; f[1] = t.y;
    t = __bfloat1622float2(*(__nv_bfloat162*)&v.y); f[2] = t.x; f[3] = t.y;
    t = __bfloat1622float2(*(__nv_bfloat162*)&v.z); f[4] = t.x; f[5] = t.y;
    t = __bfloat1622float2(*(__nv_bfloat162*)&v.w); f[6] = t.x; f[7] = t.y;
}

// ---------------------------------------------------------------------------
// Shared-memory geometry for the 128x256 GEMM tile, K-chunks of 32.
// Row stride 36 floats; A: 128x36, B: 256x36; double-buffered.
// ---------------------------------------------------------------------------
#define SM_ASTRIDE 36
#define SM_BOFF    4608
#define SM_BUF_F   13824
#define SM_BYTES   110592

// stage fp32 A + fp32 B chunk via cp.async (proj path)
__device__ __forceinline__ void stage_chunk(const float* __restrict__ A,
                                            const float* __restrict__ B,
                                            int k0, float* buf) {
    int tid = threadIdx.x;
    float* sA = buf;
    float* sB = buf + SM_BOFF;
#pragma unroll
    for (int i = 0; i < 4; i++) {
        int slot = tid + i * 256;
        int row = slot >> 3, kq = slot & 7;
        cp16(sA + row * SM_ASTRIDE + kq * 4, A + (size_t)row * 256 + k0 + kq * 4);
    }
#pragma unroll
    for (int i = 0; i < 8; i++) {
        int slot = tid + i * 256;
        int row = slot >> 3, kq = slot & 7;
        cp16(sB + row * SM_ASTRIDE + kq * 4, B + (size_t)row * 256 + k0 + kq * 4);
    }
    asm volatile("cp.async.commit_group;");
}

// stage bf16 A (ld+cvt+sts) + fp32 B chunk via cp.async (out path)
__device__ __forceinline__ void stage_chunk_bf16A(const __nv_bfloat16* __restrict__ A,
                                                  const float* __restrict__ B,
                                                  int k0, float* buf) {
    int tid = threadIdx.x;
    float* sA = buf;
    float* sB = buf + SM_BOFF;
#pragma unroll
    for (int i = 0; i < 8; i++) {
        int slot = tid + i * 256;
        int row = slot >> 3, kq = slot & 7;
        cp16(sB + row * SM_ASTRIDE + kq * 4, B + (size_t)row * 256 + k0 + kq * 4);
    }
    asm volatile("cp.async.commit_group;");
#pragma unroll
    for (int i = 0; i < 2; i++) {
        int slot = tid + i * 256;          // 512 slots: 128 rows x 4 uint4
        int row = slot >> 2, c8 = (slot & 3) * 8;
        uint4 v = *(const uint4*)(A + (size_t)row * 256 + k0 + c8);
        float f[8];
        bf8_to_f8(v, f);
        *(float4*)(sA + row * SM_ASTRIDE + c8)     = make_float4(f[0], f[1], f[2], f[3]);
        *(float4*)(sA + row * SM_ASTRIDE + c8 + 4) = make_float4(f[4], f[5], f[6], f[7]);
    }
}

__device__ __forceinline__ void compute_chunk(const float* buf, float acc[4][8][4],
                                              int wm, int wn, int g, int tg) {
    const float* As = buf;
    const float* Bs = buf + SM_BOFF;
#pragma unroll
    for (int ks = 0; ks < 4; ks++) {
        int kc = ks * 8 + tg;
        uint32_t a[4][4], b[8][2];
#pragma unroll
        for (int mt = 0; mt < 4; mt++) {
            const float* p = As + (wm * 64 + mt * 16 + g) * SM_ASTRIDE + kc;
            a[mt][0] = __float_as_uint(p[0]);
            a[mt][1] = __float_as_uint(p[8 * SM_ASTRIDE]);
            a[mt][2] = __float_as_uint(p[4]);
            a[mt][3] = __float_as_uint(p[8 * SM_ASTRIDE + 4]);
        }
#pragma unroll
        for (int nt = 0; nt < 8; nt++) {
            const float* p = Bs + (wn * 64 + nt * 8 + g) * SM_ASTRIDE + kc;
            b[nt][0] = __float_as_uint(p[0]);
            b[nt][1] = __float_as_uint(p[4]);
        }
#pragma unroll
        for (int mt = 0; mt < 4; mt++)
#pragma unroll
            for (int nt = 0; nt < 8; nt++)
                mma16n8k8(acc[mt][nt], a[mt], b[nt]);
    }
}

// ---------------------------------------------------------------------------
// Kernel 1: LayerNorm over D=256 with implicit [S,R]->[R,S] transpose.
// ---------------------------------------------------------------------------
__global__ __launch_bounds__(256) void ln_kernel(const float* __restrict__ M_raw,
                                                 const float* __restrict__ lns,
                                                 const float* __restrict__ lnb) {
    int n    = (blockIdx.x * 256 + threadIdx.x) >> 5;
    int lane = threadIdx.x & 31;
    int r = n >> 8;
    int s = n & 255;
    const float* src = M_raw + ((size_t)s * R_DIM + r) * D_DIM;

    float v[8];
#pragma unroll
    for (int i = 0; i < 8; i++) v[i] = src[lane + 32 * i];

    float sum = 0.f;
#pragma unroll
    for (int i = 0; i < 8; i++) sum += v[i];
#pragma unroll
    for (int o = 16; o > 0; o >>= 1) sum += __shfl_xor_sync(0xffffffff, sum, o);
    float mean = sum * (1.0f / 256.0f);

    float var = 0.f;
#pragma unroll
    for (int i = 0; i < 8; i++) { float d = v[i] - mean; var += d * d; }
#pragma unroll
    for (int o = 16; o > 0; o >>= 1) var += __shfl_xor_sync(0xffffffff, var, o);
    var *= (1.0f / 256.0f);
    float inv = rsqrtf(var + 1e-5f);

    float* dst = g_Mn + (size_t)n * D_DIM;
#pragma unroll
    for (int i = 0; i < 8; i++) {
        int d = lane + 32 * i;
        dst[d] = (v[i] - mean) * inv * lns[d] + lnb[d];
    }
}

// ---------------------------------------------------------------------------
// Kernel 2: fused QKVG projection via mma.sync tf32; bf16 output.
// grid (4, 1024): x = matrix — concurrent CTAs share the A tile via L2.
// ---------------------------------------------------------------------------
__global__ __launch_bounds__(256) void proj_mma(const float* __restrict__ Wq,
                                                const float* __restrict__ Wk,
                                                const float* __restrict__ Wv,
                                                const float* __restrict__ Wg,
                                                const float* __restrict__ bg) {
    extern __shared__ float smf[];
    int mat = blockIdx.x;
    int by  = blockIdx.y;
    const float* W = (mat == 0) ? Wq : (mat == 1) ? Wk : (mat == 2) ? Wv : Wg;
    const float* Abase = g_Mn + (size_t)by * 128 * 256;

    int tid = threadIdx.x, wid = tid >> 5, lane = tid & 31;
    int g = lane >> 2, tg = lane & 3;
    int wm = wid & 1, wn = wid >> 1;

    float acc[4][8][4];
#pragma unroll
    for (int mt = 0; mt < 4; mt++)
#pragma unroll
        for (int nt = 0; nt < 8; nt++)
#pragma unroll
            for (int i = 0; i < 4; i++) acc[mt][nt][i] = 0.f;

    stage_chunk(Abase, W, 0, smf);
    stage_chunk(Abase, W, 32, smf + SM_BUF_F);

#pragma unroll 1
    for (int c = 0; c < 8; c++) {
        if (c == 7) asm volatile("cp.async.wait_group 0;" ::: "memory");
        else        asm volatile("cp.async.wait_group 1;" ::: "memory");
        __syncthreads();
        compute_chunk(smf + (c & 1) * SM_BUF_F, acc, wm, wn, g, tg);
        __syncthreads();
        if (c + 2 < 8) stage_chunk(Abase, W, (c + 2) * 32, smf + (c & 1) * SM_BUF_F);
    }

    int row0 = by * 128 + wm * 64;
#pragma unroll
    for (int mt = 0; mt < 4; mt++) {
#pragma unroll
        for (int nt = 0; nt < 8; nt++) {
            int col = wn * 64 + nt * 8 + 2 * tg;
            float v0 = acc[mt][nt][0], v1 = acc[mt][nt][1];
            float v2 = acc[mt][nt][2], v3 = acc[mt][nt][3];
            if (mat == 0) {
                v0 *= Q_SCALE_LOG2E; v1 *= Q_SCALE_LOG2E;
                v2 *= Q_SCALE_LOG2E; v3 *= Q_SCALE_LOG2E;
            } else if (mat == 3) {
                float b0 = bg[col], b1 = bg[col + 1];
                v0 = 1.f / (1.f + __expf(-(v0 + b0)));
                v1 = 1.f / (1.f + __expf(-(v1 + b1)));
                v2 = 1.f / (1.f + __expf(-(v2 + b0)));
                v3 = 1.f / (1.f + __expf(-(v3 + b1)));
            }
            size_t i0 = (size_t)(row0 + mt * 16 + g) * 1024 + mat * 256 + col;
            *(__nv_bfloat162*)(g_QKVG + i0)            = __floats2bfloat162_rn(v0, v1);
            *(__nv_bfloat162*)(g_QKVG + i0 + 8 * 1024) = __floats2bfloat162_rn(v2, v3);
        }
    }
}

// ---------------------------------------------------------------------------
// Kernel 3: tensor-core attention (tf32 mma, unchanged fragment paths).
// bf16 global input staged + converted to fp32 smem tiles; bf16 output.
// SMEM: Qs 256x36 @0, Ks 256x36 @9216, Vs 256x40 @18432, Ps 8x(32x68) @28672.
// ---------------------------------------------------------------------------
#define AT_SMEM_BYTES 184320

__global__ __launch_bounds__(256) void attn_mma() {
    extern __shared__ float sm[];
    float* Qs = sm;
    float* Ks = sm + 9216;
    float* Vs = sm + 18432;

    int tid = threadIdx.x, wid = tid >> 5, lane = tid & 31;
    int g = lane >> 2, tg = lane & 3;
    float* Ps = sm + 28672 + wid * 2176;

    int h = blockIdx.x;
    int r = blockIdx.y;
    const __nv_bfloat16* base = g_QKVG + (size_t)r * 256 * 1024 + h * 32;

    // ---- stage q/k/v tiles (bf16 -> fp32 smem) ---------------------------
#pragma unroll
    for (int i = 0; i < 4; i++) {
        int slot = tid + i * 256;          // 1024 slots: 256 rows x 4 uint4
        int row = slot >> 2, c8 = (slot & 3) * 8;
        const __nv_bfloat16* gsrc = base + (size_t)row * 1024 + c8;
        uint4 qv = *(const uint4*)(gsrc);
        uint4 kv = *(const uint4*)(gsrc + 256);
        uint4 vv = *(const uint4*)(gsrc + 512);
        float f[8];
        bf8_to_f8(qv, f);
        *(float4*)(Qs + row * 36 + c8)     = make_float4(f[0], f[1], f[2], f[3]);
        *(float4*)(Qs + row * 36 + c8 + 4) = make_float4(f[4], f[5], f[6], f[7]);
        bf8_to_f8(kv, f);
        *(float4*)(Ks + row * 36 + c8)     = make_float4(f[0], f[1], f[2], f[3]);
        *(float4*)(Ks + row * 36 + c8 + 4) = make_float4(f[4], f[5], f[6], f[7]);
        bf8_to_f8(vv, f);
        *(float4*)(Vs + row * 40 + c8)     = make_float4(f[0], f[1], f[2], f[3]);
        *(float4*)(Vs + row * 40 + c8 + 4) = make_float4(f[4], f[5], f[6], f[7]);
    }
    __syncthreads();

    // ---- q fragments (persistent) ----------------------------------------
    uint32_t qa[2][4][4];
#pragma unroll
    for (int mt = 0; mt < 2; mt++)
#pragma unroll
        for (int ks = 0; ks < 4; ks++) {
            const float* p = Qs + (wid * 32 + mt * 16 + g) * 36 + ks * 8 + tg;
            qa[mt][ks][0] = __float_as_uint(p[0]);
            qa[mt][ks][1] = __float_as_uint(p[8 * 36]);
            qa[mt][ks][2] = __float_as_uint(p[4]);
            qa[mt][ks][3] = __float_as_uint(p[8 * 36 + 4]);
        }

    float acc_o[2][4][4];
#pragma unroll
    for (int mt = 0; mt < 2; mt++)
#pragma unroll
        for (int nt = 0; nt < 4; nt++)
#pragma unroll
            for (int i = 0; i < 4; i++) acc_o[mt][nt][i] = 0.f;
    float lrow[2][2] = {{0.f, 0.f}, {0.f, 0.f}};

    // ---- main loop over 4 key blocks of 64 --------------------------------
#pragma unroll 1
    for (int jb = 0; jb < 4; jb++) {
        float accl[2][8][4];
#pragma unroll
        for (int mt = 0; mt < 2; mt++)
#pragma unroll
            for (int nt = 0; nt < 8; nt++)
#pragma unroll
                for (int i = 0; i < 4; i++) accl[mt][nt][i] = 0.f;

        // logits: q[32,32] @ K[64,32]^T
#pragma unroll
        for (int ks = 0; ks < 4; ks++) {
            uint32_t b[8][2];
#pragma unroll
            for (int nt = 0; nt < 8; nt++) {
                const float* p = Ks + (jb * 64 + nt * 8 + g) * 36 + ks * 8 + tg;
                b[nt][0] = __float_as_uint(p[0]);
                b[nt][1] = __float_as_uint(p[4]);
            }
#pragma unroll
            for (int mt = 0; mt < 2; mt++)
#pragma unroll
                for (int nt = 0; nt < 8; nt++)
                    mma16n8k8(accl[mt][nt], qa[mt][ks], b[nt]);
        }

        // exp2, accumulate l, store P block
#pragma unroll
        for (int mt = 0; mt < 2; mt++)
#pragma unroll
            for (int nt = 0; nt < 8; nt++) {
                float p0 = ex2_approx(accl[mt][nt][0]);
                float p1 = ex2_approx(accl[mt][nt][1]);
                float p2 = ex2_approx(accl[mt][nt][2]);
                float p3 = ex2_approx(accl[mt][nt][3]);
                lrow[mt][0] += p0 + p1;
                lrow[mt][1] += p2 + p3;
                int col = nt * 8 + 2 * tg;
                *(float2*)(Ps + (mt * 16 + g) * 68 + col)     = make_float2(p0, p1);
                *(float2*)(Ps + (mt * 16 + g + 8) * 68 + col) = make_float2(p2, p3);
            }
        __syncwarp();

        // o += P[32,64] @ V[64,32]
#pragma unroll
        for (int ks = 0; ks < 8; ks++) {
            uint32_t a[2][4], b[4][2];
#pragma unroll
            for (int mt = 0; mt < 2; mt++) {
                const float* p = Ps + (mt * 16 + g) * 68 + ks * 8 + tg;
                a[mt][0] = __float_as_uint(p[0]);
                a[mt][1] = __float_as_uint(p[8 * 68]);
                a[mt][2] = __float_as_uint(p[4]);
                a[mt][3] = __float_as_uint(p[8 * 68 + 4]);
            }
#pragma unroll
            for (int nt = 0; nt < 4; nt++) {
                const float* p = Vs + (jb * 64 + ks * 8 + tg) * 40 + nt * 8 + g;
                b[nt][0] = __float_as_uint(p[0]);
                b[nt][1] = __float_as_uint(p[4 * 40]);
            }
#pragma unroll
            for (int mt = 0; mt < 2; mt++)
#pragma unroll
                for (int nt = 0; nt < 4; nt++)
                    mma16n8k8(acc_o[mt][nt], a[mt], b[nt]);
        }
        __syncwarp();
    }

    // ---- reduce l across the tg quad --------------------------------------
#pragma unroll
    for (int mt = 0; mt < 2; mt++)
#pragma unroll
        for (int hh = 0; hh < 2; hh++) {
            float l = lrow[mt][hh];
            l += __shfl_xor_sync(0xffffffff, l, 1);
            l += __shfl_xor_sync(0xffffffff, l, 2);
            lrow[mt][hh] = 1.0f / l;
        }

    // ---- normalize, gate (bf16), store bf16 -------------------------------
#pragma unroll
    for (int mt = 0; mt < 2; mt++) {
        int row_lo = wid * 32 + mt * 16 + g;
        int row_hi = row_lo + 8;
#pragma unroll
        for (int nt = 0; nt < 4; nt++) {
            int col = nt * 8 + 2 * tg;
            float2 g0 = __bfloat1622float2(
                *(const __nv_bfloat162*)(base + (size_t)row_lo * 1024 + 768 + col));
            float2 g1 = __bfloat1622float2(
                *(const __nv_bfloat162*)(base + (size_t)row_hi * 1024 + 768 + col));
            float o0x = acc_o[mt][nt][0] * lrow[mt][0] * g0.x;
            float o0y = acc_o[mt][nt][1] * lrow[mt][0] * g0.y;
            float o1x = acc_o[mt][nt][2] * lrow[mt][1] * g1.x;
            float o1y = acc_o[mt][nt][3] * lrow[mt][1] * g1.y;
            size_t i0 = ((size_t)(r * 256 + row_lo)) * 256 + h * 32 + col;
            size_t i1 = ((size_t)(r * 256 + row_hi)) * 256 + h * 32 + col;
            *(__nv_bfloat162*)(g_O + i0) = __floats2bfloat162_rn(o0x, o0y);
            *(__nv_bfloat162*)(g_O + i1) = __floats2bfloat162_rn(o1x, o1y);
        }
    }
}

// ---------------------------------------------------------------------------
// Kernel 4: output projection (A = bf16 g_O) + bias + residual + transpose.
// ---------------------------------------------------------------------------
__global__ __launch_bounds__(256) void out_mma(const float* __restrict__ Wo,
                                               const float* __restrict__ bo,
                                               const float* __restrict__ M_raw,
                                               float* __restrict__ out) {
    extern __shared__ float smf[];
    int by = blockIdx.x;
    const __nv_bfloat16* Abase = g_O + (size_t)by * 128 * 256;

    int tid = threadIdx.x, wid = tid >> 5, lane = tid & 31;
    int g = lane >> 2, tg = lane & 3;
    int wm = wid & 1, wn = wid >> 1;

    float acc[4][8][4];
#pragma unroll
    for (int mt = 0; mt < 4; mt++)
#pragma unroll
        for (int nt = 0; nt < 8; nt++)
#pragma unroll
            for (int i = 0; i < 4; i++) acc[mt][nt][i] = 0.f;

    stage_chunk_bf16A(Abase, Wo, 0, smf);
    stage_chunk_bf16A(Abase, Wo, 32, smf + SM_BUF_F);

#pragma unroll 1
    for (int c = 0; c < 8; c++) {
        if (c == 7) asm volatile("cp.async.wait_group 0;" ::: "memory");
        else        asm volatile("cp.async.wait_group 1;" ::: "memory");
        __syncthreads();
        compute_chunk(smf + (c & 1) * SM_BUF_F, acc, wm, wn, g, tg);
        __syncthreads();
        if (c + 2 < 8) stage_chunk_bf16A(Abase, Wo, (c + 2) * 32, smf + (c & 1) * SM_BUF_F);
    }

    int row0 = by * 128 + wm * 64;
#pragma unroll
    for (int mt = 0; mt < 4; mt++) {
        int n0 = row0 + mt * 16 + g;
        int rr = n0 >> 8, ss = n0 & 255;
#pragma unroll
        for (int nt = 0; nt < 8; nt++) {
            int d = wn * 64 + nt * 8 + 2 * tg;
            float b0 = bo[d], b1 = bo[d + 1];
            size_t i0 = ((size_t)ss * R_DIM + rr) * D_DIM + d;
            size_t i1 = ((size_t)(ss + 8) * R_DIM + rr) * D_DIM + d;
            float2 m0 = *(const float2*)(M_raw + i0);
            float2 m1 = *(const float2*)(M_raw + i1);
            *(float2*)(out + i0) = make_float2(acc[mt][nt][0] + b0 + m0.x,
                                               acc[mt][nt][1] + b1 + m0.y);
            *(float2*)(out + i1) = make_float2(acc[mt][nt][2] + b0 + m1.x,
                                               acc[mt][nt][3] + b1 + m1.y);
        }
    }
}

// ---------------------------------------------------------------------------
extern "C" void kernel_launch(void* const* d_in, const int* in_sizes, int n_in,
                              void* d_out, int out_size) {
    const float* M_raw = (const float*)d_in[0];
    const float* lns   = (const float*)d_in[1];
    const float* lnb   = (const float*)d_in[2];
    const float* Wq    = (const float*)d_in[3];
    const float* Wk    = (const float*)d_in[4];
    const float* Wv    = (const float*)d_in[5];
    const float* Wg    = (const float*)d_in[6];
    const float* bg    = (const float*)d_in[7];
    const float* Wo    = (const float*)d_in[8];
    const float* bo    = (const float*)d_in[9];
    float* out = (float*)d_out;

    cudaFuncSetAttribute(proj_mma, cudaFuncAttributeMaxDynamicSharedMemorySize, SM_BYTES);
    cudaFuncSetAttribute(out_mma,  cudaFuncAttributeMaxDynamicSharedMemorySize, SM_BYTES);
    cudaFuncSetAttribute(attn_mma, cudaFuncAttributeMaxDynamicSharedMemorySize, AT_SMEM_BYTES);

    ln_kernel<<<NROWS / 8, 256>>>(M_raw, lns, lnb);

    dim3 gp(4, NROWS / 128);
    proj_mma<<<gp, 256, SM_BYTES>>>(Wq, Wk, Wv, Wg, bg);

    dim3 ga(8, R_DIM);
    attn_mma<<<ga, 256, AT_SMEM_BYTES>>>();

    out_mma<<<NROWS / 128, 256, SM_BYTES>>>(Wo, bo, M_raw, out);
}

// round 16
// speedup vs baseline: 2.0460x; 2.0460x over previous
#include <cuda_runtime.h>
#include <cuda_bf16.h>
#include <stdint.h>

#define R_DIM 512
#define S_DIM 256
#define D_DIM 256
#define NROWS (R_DIM * S_DIM)        // 131072

// ---------------- scratch (static device arrays; no cudaMalloc) ------------
__device__ __nv_bfloat16 g_Mn[NROWS * D_DIM];             // layernormed M (bf16)
__device__ __nv_bfloat16 g_QKVG[(size_t)NROWS * 1024];    // q|k|v|gate (bf16)
__device__ __nv_bfloat16 g_O[NROWS * D_DIM];              // gated attn out (bf16)
__device__ __nv_bfloat16 g_Wb[5 * 65536];                 // Wq|Wk|Wv|Wg|Wo (bf16)

// q scale: C^-0.5 * log2(e) — attention uses exp2
#define Q_SCALE_LOG2E 0.2550348658f

// ---------------------------------------------------------------------------
// mma.sync bf16 + cp.async helpers (base PTX target)
// ---------------------------------------------------------------------------
__device__ __forceinline__ void mma_bf16(float* d, const uint32_t* a, const uint32_t* b) {
    asm volatile("mma.sync.aligned.m16n8k16.row.col.f32.bf16.bf16.f32 "
        "{%0,%1,%2,%3}, {%4,%5,%6,%7}, {%8,%9}, {%0,%1,%2,%3};"
        : "+f"(d[0]), "+f"(d[1]), "+f"(d[2]), "+f"(d[3])
        : "r"(a[0]), "r"(a[1]), "r"(a[2]), "r"(a[3]), "r"(b[0]), "r"(b[1]));
}

__device__ __forceinline__ void cp16(const void* sdst, const void* gsrc) {
    uint32_t d = (uint32_t)__cvta_generic_to_shared(sdst);
    asm volatile("cp.async.cg.shared.global [%0], [%1], 16;" :: "r"(d), "l"(gsrc));
}

__device__ __forceinline__ float ex2_approx(float x) {
    float y;
    asm("ex2.approx.ftz.f32 %0, %1;" : "=f"(y) : "f"(x));
    return y;
}

// ---------------------------------------------------------------------------
// Shared-memory geometry for the 128x256 bf16 GEMM tile, K-chunks of 32.
// Row stride 72 bf16 (144 B): fragment loads bank-conflict-free ((4g+tg)%32).
// A: 128x72, B: 256x72 bf16; double-buffered.
// ---------------------------------------------------------------------------
#define GS_STRIDE 72
#define GS_BOFF   9216
#define GS_BUF    27648                 // bf16 elems per buffer
#define GS_BYTES  110592

__device__ __forceinline__ void stage_chunk(const __nv_bfloat16* __restrict__ A,
                                            const __nv_bfloat16* __restrict__ B,
                                            int k0, __nv_bfloat16* buf) {
    int tid = threadIdx.x;
    __nv_bfloat16* sA = buf;
    __nv_bfloat16* sB = buf + GS_BOFF;
#pragma unroll
    for (int i = 0; i < 2; i++) {          // A: 128 rows x 4 slots of 8 bf16
        int slot = tid + i * 256;
        int row = slot >> 2, kq = (slot & 3) * 8;
        cp16(sA + row * GS_STRIDE + kq, A + (size_t)row * 256 + k0 + kq);
    }
#pragma unroll
    for (int i = 0; i < 4; i++) {          // B: 256 rows x 4 slots
        int slot = tid + i * 256;
        int row = slot >> 2, kq = (slot & 3) * 8;
        cp16(sB + row * GS_STRIDE + kq, B + (size_t)row * 256 + k0 + kq);
    }
    asm volatile("cp.async.commit_group;");
}

__device__ __forceinline__ void compute_chunk(const __nv_bfloat16* buf, float acc[4][8][4],
                                              int wm, int wn, int g, int tg) {
    const __nv_bfloat16* As = buf;
    const __nv_bfloat16* Bs = buf + GS_BOFF;
#pragma unroll
    for (int ks = 0; ks < 2; ks++) {       // 2 x K=16 per 32-chunk
        int kc = ks * 16 + 2 * tg;
        uint32_t a[4][4], b[8][2];
#pragma unroll
        for (int mt = 0; mt < 4; mt++) {
            const __nv_bfloat16* p = As + (wm * 64 + mt * 16 + g) * GS_STRIDE + kc;
            a[mt][0] = *(const uint32_t*)(p);
            a[mt][1] = *(const uint32_t*)(p + 8 * GS_STRIDE);
            a[mt][2] = *(const uint32_t*)(p + 8);
            a[mt][3] = *(const uint32_t*)(p + 8 * GS_STRIDE + 8);
        }
#pragma unroll
        for (int nt = 0; nt < 8; nt++) {
            const __nv_bfloat16* p = Bs + (wn * 64 + nt * 8 + g) * GS_STRIDE + kc;
            b[nt][0] = *(const uint32_t*)(p);
            b[nt][1] = *(const uint32_t*)(p + 8);
        }
#pragma unroll
        for (int mt = 0; mt < 4; mt++)
#pragma unroll
            for (int nt = 0; nt < 8; nt++)
                mma_bf16(acc[mt][nt], a[mt], b[nt]);
    }
}

__device__ __forceinline__ void gemm_128x256(const __nv_bfloat16* __restrict__ Abase,
                                             const __nv_bfloat16* __restrict__ Bbase,
                                             float acc[4][8][4]) {
    extern __shared__ __nv_bfloat16 smb[];
    int tid = threadIdx.x, wid = tid >> 5, lane = tid & 31;
    int g = lane >> 2, tg = lane & 3;
    int wm = wid & 1, wn = wid >> 1;

#pragma unroll
    for (int mt = 0; mt < 4; mt++)
#pragma unroll
        for (int nt = 0; nt < 8; nt++)
#pragma unroll
            for (int i = 0; i < 4; i++) acc[mt][nt][i] = 0.f;

    stage_chunk(Abase, Bbase, 0, smb);
    stage_chunk(Abase, Bbase, 32, smb + GS_BUF);

#pragma unroll 1
    for (int c = 0; c < 8; c++) {
        if (c == 7) asm volatile("cp.async.wait_group 0;" ::: "memory");
        else        asm volatile("cp.async.wait_group 1;" ::: "memory");
        __syncthreads();
        compute_chunk(smb + (c & 1) * GS_BUF, acc, wm, wn, g, tg);
        __syncthreads();
        if (c + 2 < 8) stage_chunk(Abase, Bbase, (c + 2) * 32, smb + (c & 1) * GS_BUF);
    }
}

// ---------------------------------------------------------------------------
// Kernel 0: convert the 5 weight matrices fp32 -> bf16 (runs every launch).
// 327680 elems, 4 per thread.
// ---------------------------------------------------------------------------
__global__ __launch_bounds__(256) void cvt_w(const float* __restrict__ Wq,
                                             const float* __restrict__ Wk,
                                             const float* __restrict__ Wv,
                                             const float* __restrict__ Wg,
                                             const float* __restrict__ Wo) {
    int idx = (blockIdx.x * 256 + threadIdx.x) * 4;
    int mat = idx >> 16, off = idx & 65535;
    const float* src = (mat == 0) ? Wq : (mat == 1) ? Wk : (mat == 2) ? Wv
                     : (mat == 3) ? Wg : Wo;
    float4 v = *(const float4*)(src + off);
    *(__nv_bfloat162*)(g_Wb + idx)     = __floats2bfloat162_rn(v.x, v.y);
    *(__nv_bfloat162*)(g_Wb + idx + 2) = __floats2bfloat162_rn(v.z, v.w);
}

// ---------------------------------------------------------------------------
// Kernel 1: LayerNorm over D=256 with implicit [S,R]->[R,S] transpose; bf16 out.
// ---------------------------------------------------------------------------
__global__ __launch_bounds__(256) void ln_kernel(const float* __restrict__ M_raw,
                                                 const float* __restrict__ lns,
                                                 const float* __restrict__ lnb) {
    int n    = (blockIdx.x * 256 + threadIdx.x) >> 5;
    int lane = threadIdx.x & 31;
    int r = n >> 8;
    int s = n & 255;
    const float* src = M_raw + ((size_t)s * R_DIM + r) * D_DIM;

    float v[8];
#pragma unroll
    for (int i = 0; i < 8; i++) v[i] = src[lane + 32 * i];

    float sum = 0.f;
#pragma unroll
    for (int i = 0; i < 8; i++) sum += v[i];
#pragma unroll
    for (int o = 16; o > 0; o >>= 1) sum += __shfl_xor_sync(0xffffffff, sum, o);
    float mean = sum * (1.0f / 256.0f);

    float var = 0.f;
#pragma unroll
    for (int i = 0; i < 8; i++) { float d = v[i] - mean; var += d * d; }
#pragma unroll
    for (int o = 16; o > 0; o >>= 1) var += __shfl_xor_sync(0xffffffff, var, o);
    var *= (1.0f / 256.0f);
    float inv = rsqrtf(var + 1e-5f);

    __nv_bfloat16* dst = g_Mn + (size_t)n * D_DIM;
#pragma unroll
    for (int i = 0; i < 8; i++) {
        int d = lane + 32 * i;
        dst[d] = __float2bfloat16((v[i] - mean) * inv * lns[d] + lnb[d]);
    }
}

// ---------------------------------------------------------------------------
// Kernel 2: fused QKVG projection via bf16 mma; bf16 output.
// grid (4, 1024): x = matrix — adjacent CTAs share the A tile via L2.
// ---------------------------------------------------------------------------
__global__ __launch_bounds__(256) void proj_mma(const float* __restrict__ bg) {
    int mat = blockIdx.x;
    int by  = blockIdx.y;

    float acc[4][8][4];
    gemm_128x256(g_Mn + (size_t)by * 128 * 256, g_Wb + mat * 65536, acc);

    int tid = threadIdx.x, wid = tid >> 5, lane = tid & 31;
    int g = lane >> 2, tg = lane & 3;
    int wm = wid & 1, wn = wid >> 1;
    int row0 = by * 128 + wm * 64;

#pragma unroll
    for (int mt = 0; mt < 4; mt++) {
#pragma unroll
        for (int nt = 0; nt < 8; nt++) {
            int col = wn * 64 + nt * 8 + 2 * tg;
            float v0 = acc[mt][nt][0], v1 = acc[mt][nt][1];
            float v2 = acc[mt][nt][2], v3 = acc[mt][nt][3];
            if (mat == 0) {
                v0 *= Q_SCALE_LOG2E; v1 *= Q_SCALE_LOG2E;
                v2 *= Q_SCALE_LOG2E; v3 *= Q_SCALE_LOG2E;
            } else if (mat == 3) {
                float b0 = bg[col], b1 = bg[col + 1];
                v0 = 1.f / (1.f + __expf(-(v0 + b0)));
                v1 = 1.f / (1.f + __expf(-(v1 + b1)));
                v2 = 1.f / (1.f + __expf(-(v2 + b0)));
                v3 = 1.f / (1.f + __expf(-(v3 + b1)));
            }
            size_t i0 = (size_t)(row0 + mt * 16 + g) * 1024 + mat * 256 + col;
            *(__nv_bfloat162*)(g_QKVG + i0)            = __floats2bfloat162_rn(v0, v1);
            *(__nv_bfloat162*)(g_QKVG + i0 + 8 * 1024) = __floats2bfloat162_rn(v2, v3);
        }
    }
}

// ---------------------------------------------------------------------------
// Kernel 3: tensor-core attention, all-bf16 tiles + bf16 mma.
// CTA per (r,h), 8 warps, 32 q rows/warp. Tiles stride 72 bf16 (144 B):
//   A/B frag 4B loads: banks (4g+tg) distinct;
//   V k-major 2B gathers: banks (8tg+g/2) distinct;  P store: (4g+4nt+tg).
// SMEM (bf16 elems): Qs@0, Ks@18432, Vs@36864, Ps@55296 + wid*2304.
// Total 73728 bf16 = 147456 B.
// ---------------------------------------------------------------------------
#define AT_SMEM_BYTES 147456

__global__ __launch_bounds__(256) void attn_mma() {
    extern __shared__ __nv_bfloat16 smb[];
    __nv_bfloat16* Qs = smb;
    __nv_bfloat16* Ks = smb + 18432;
    __nv_bfloat16* Vs = smb + 36864;

    int tid = threadIdx.x, wid = tid >> 5, lane = tid & 31;
    int g = lane >> 2, tg = lane & 3;
    __nv_bfloat16* Ps = smb + 55296 + wid * 2304;

    int h = blockIdx.x;
    int r = blockIdx.y;
    const __nv_bfloat16* base = g_QKVG + (size_t)r * 256 * 1024 + h * 32;

    // ---- stage q/k/v tiles via cp.async ----------------------------------
#pragma unroll
    for (int i = 0; i < 4; i++) {
        int slot = tid + i * 256;              // 1024: 256 rows x 4 slots of 8
        int row = slot >> 2, c8 = (slot & 3) * 8;
        const __nv_bfloat16* gsrc = base + (size_t)row * 1024 + c8;
        cp16(Qs + row * 72 + c8, gsrc);
        cp16(Ks + row * 72 + c8, gsrc + 256);
        cp16(Vs + row * 72 + c8, gsrc + 512);
    }
    asm volatile("cp.async.commit_group;");
    asm volatile("cp.async.wait_group 0;" ::: "memory");
    __syncthreads();

    // ---- q fragments (persistent): 2 m-tiles x 2 k-steps ------------------
    uint32_t qa[2][2][4];
#pragma unroll
    for (int mt = 0; mt < 2; mt++)
#pragma unroll
        for (int ks = 0; ks < 2; ks++) {
            const __nv_bfloat16* p = Qs + (wid * 32 + mt * 16 + g) * 72 + ks * 16 + 2 * tg;
            qa[mt][ks][0] = *(const uint32_t*)(p);
            qa[mt][ks][1] = *(const uint32_t*)(p + 8 * 72);
            qa[mt][ks][2] = *(const uint32_t*)(p + 8);
            qa[mt][ks][3] = *(const uint32_t*)(p + 8 * 72 + 8);
        }

    float acc_o[2][4][4];
#pragma unroll
    for (int mt = 0; mt < 2; mt++)
#pragma unroll
        for (int nt = 0; nt < 4; nt++)
#pragma unroll
            for (int i = 0; i < 4; i++) acc_o[mt][nt][i] = 0.f;
    float lrow[2][2] = {{0.f, 0.f}, {0.f, 0.f}};

    // ---- main loop over 4 key blocks of 64 --------------------------------
#pragma unroll 1
    for (int jb = 0; jb < 4; jb++) {
        float accl[2][8][4];
#pragma unroll
        for (int mt = 0; mt < 2; mt++)
#pragma unroll
            for (int nt = 0; nt < 8; nt++)
#pragma unroll
                for (int i = 0; i < 4; i++) accl[mt][nt][i] = 0.f;

        // logits: q[32,32] @ K[64,32]^T  (2 k-steps of 16)
#pragma unroll
        for (int ks = 0; ks < 2; ks++) {
            uint32_t b[8][2];
#pragma unroll
            for (int nt = 0; nt < 8; nt++) {
                const __nv_bfloat16* p = Ks + (jb * 64 + nt * 8 + g) * 72 + ks * 16 + 2 * tg;
                b[nt][0] = *(const uint32_t*)(p);
                b[nt][1] = *(const uint32_t*)(p + 8);
            }
#pragma unroll
            for (int mt = 0; mt < 2; mt++)
#pragma unroll
                for (int nt = 0; nt < 8; nt++)
                    mma_bf16(accl[mt][nt], qa[mt][ks], b[nt]);
        }

        // exp2, accumulate l, store P block as bf16 (C-frag -> row-major)
#pragma unroll
        for (int mt = 0; mt < 2; mt++)
#pragma unroll
            for (int nt = 0; nt < 8; nt++) {
                float p0 = ex2_approx(accl[mt][nt][0]);
                float p1 = ex2_approx(accl[mt][nt][1]);
                float p2 = ex2_approx(accl[mt][nt][2]);
                float p3 = ex2_approx(accl[mt][nt][3]);
                lrow[mt][0] += p0 + p1;
                lrow[mt][1] += p2 + p3;
                int col = nt * 8 + 2 * tg;
                *(__nv_bfloat162*)(Ps + (mt * 16 + g) * 72 + col)     = __floats2bfloat162_rn(p0, p1);
                *(__nv_bfloat162*)(Ps + (mt * 16 + g + 8) * 72 + col) = __floats2bfloat162_rn(p2, p3);
            }
        __syncwarp();

        // o += P[32,64] @ V[64,32]  (4 k-steps of 16)
#pragma unroll
        for (int ks = 0; ks < 4; ks++) {
            uint32_t a[2][4], b[4][2];
#pragma unroll
            for (int mt = 0; mt < 2; mt++) {
                const __nv_bfloat16* p = Ps + (mt * 16 + g) * 72 + ks * 16 + 2 * tg;
                a[mt][0] = *(const uint32_t*)(p);
                a[mt][1] = *(const uint32_t*)(p + 8 * 72);
                a[mt][2] = *(const uint32_t*)(p + 8);
                a[mt][3] = *(const uint32_t*)(p + 8 * 72 + 8);
            }
#pragma unroll
            for (int nt = 0; nt < 4; nt++) {
                const unsigned short* vp = (const unsigned short*)
                    (Vs + (jb * 64 + ks * 16 + 2 * tg) * 72 + nt * 8 + g);
                b[nt][0] = (uint32_t)vp[0]      | ((uint32_t)vp[72]     << 16);
                b[nt][1] = (uint32_t)vp[8 * 72] | ((uint32_t)vp[9 * 72] << 16);
            }
#pragma unroll
            for (int mt = 0; mt < 2; mt++)
#pragma unroll
                for (int nt = 0; nt < 4; nt++)
                    mma_bf16(acc_o[mt][nt], a[mt], b[nt]);
        }
        __syncwarp();
    }

    // ---- reduce l across the tg quad --------------------------------------
#pragma unroll
    for (int mt = 0; mt < 2; mt++)
#pragma unroll
        for (int hh = 0; hh < 2; hh++) {
            float l = lrow[mt][hh];
            l += __shfl_xor_sync(0xffffffff, l, 1);
            l += __shfl_xor_sync(0xffffffff, l, 2);
            lrow[mt][hh] = 1.0f / l;
        }

    // ---- normalize, gate, store bf16 --------------------------------------
#pragma unroll
    for (int mt = 0; mt < 2; mt++) {
        int row_lo = wid * 32 + mt * 16 + g;
        int row_hi = row_lo + 8;
#pragma unroll
        for (int nt = 0; nt < 4; nt++) {
            int col = nt * 8 + 2 * tg;
            float2 g0 = __bfloat1622float2(
                *(const __nv_bfloat162*)(base + (size_t)row_lo * 1024 + 768 + col));
            float2 g1 = __bfloat1622float2(
                *(const __nv_bfloat162*)(base + (size_t)row_hi * 1024 + 768 + col));
            float o0x = acc_o[mt][nt][0] * lrow[mt][0] * g0.x;
            float o0y = acc_o[mt][nt][1] * lrow[mt][0] * g0.y;
            float o1x = acc_o[mt][nt][2] * lrow[mt][1] * g1.x;
            float o1y = acc_o[mt][nt][3] * lrow[mt][1] * g1.y;
            size_t i0 = ((size_t)(r * 256 + row_lo)) * 256 + h * 32 + col;
            size_t i1 = ((size_t)(r * 256 + row_hi)) * 256 + h * 32 + col;
            *(__nv_bfloat162*)(g_O + i0) = __floats2bfloat162_rn(o0x, o0y);
            *(__nv_bfloat162*)(g_O + i1) = __floats2bfloat162_rn(o1x, o1y);
        }
    }
}

// ---------------------------------------------------------------------------
// Kernel 4: output projection (bf16 mma) + bias + residual + transpose.
// ---------------------------------------------------------------------------
__global__ __launch_bounds__(256) void out_mma(const float* __restrict__ bo,
                                               const float* __restrict__ M_raw,
                                               float* __restrict__ out) {
    int by = blockIdx.x;

    float acc[4][8][4];
    gemm_128x256(g_O + (size_t)by * 128 * 256, g_Wb + 4 * 65536, acc);

    int tid = threadIdx.x, wid = tid >> 5, lane = tid & 31;
    int g = lane >> 2, tg = lane & 3;
    int wm = wid & 1, wn = wid >> 1;
    int row0 = by * 128 + wm * 64;

#pragma unroll
    for (int mt = 0; mt < 4; mt++) {
        int n0 = row0 + mt * 16 + g;
        int rr = n0 >> 8, ss = n0 & 255;
#pragma unroll
        for (int nt = 0; nt < 8; nt++) {
            int d = wn * 64 + nt * 8 + 2 * tg;
            float b0 = bo[d], b1 = bo[d + 1];
            size_t i0 = ((size_t)ss * R_DIM + rr) * D_DIM + d;
            size_t i1 = ((size_t)(ss + 8) * R_DIM + rr) * D_DIM + d;
            float2 m0 = *(const float2*)(M_raw + i0);
            float2 m1 = *(const float2*)(M_raw + i1);
            *(float2*)(out + i0) = make_float2(acc[mt][nt][0] + b0 + m0.x,
                                               acc[mt][nt][1] + b1 + m0.y);
            *(float2*)(out + i1) = make_float2(acc[mt][nt][2] + b0 + m1.x,
                                               acc[mt][nt][3] + b1 + m1.y);
        }
    }
}

// ---------------------------------------------------------------------------
extern "C" void kernel_launch(void* const* d_in, const int* in_sizes, int n_in,
                              void* d_out, int out_size) {
    const float* M_raw = (const float*)d_in[0];
    const float* lns   = (const float*)d_in[1];
    const float* lnb   = (const float*)d_in[2];
    const float* Wq    = (const float*)d_in[3];
    const float* Wk    = (const float*)d_in[4];
    const float* Wv    = (const float*)d_in[5];
    const float* Wg    = (const float*)d_in[6];
    const float* bg    = (const float*)d_in[7];
    const float* Wo    = (const float*)d_in[8];
    const float* bo    = (const float*)d_in[9];
    float* out = (float*)d_out;

    cudaFuncSetAttribute(proj_mma, cudaFuncAttributeMaxDynamicSharedMemorySize, GS_BYTES);
    cudaFuncSetAttribute(out_mma,  cudaFuncAttributeMaxDynamicSharedMemorySize, GS_BYTES);
    cudaFuncSetAttribute(attn_mma, cudaFuncAttributeMaxDynamicSharedMemorySize, AT_SMEM_BYTES);

    cvt_w<<<320, 256>>>(Wq, Wk, Wv, Wg, Wo);

    ln_kernel<<<NROWS / 8, 256>>>(M_raw, lns, lnb);

    dim3 gp(4, NROWS / 128);
    proj_mma<<<gp, 256, GS_BYTES>>>(bg);

    dim3 ga(8, R_DIM);
    attn_mma<<<ga, 256, AT_SMEM_BYTES>>>();

    out_mma<<<NROWS / 128, 256, GS_BYTES>>>(bo, M_raw, out);
}

// round 17
// speedup vs baseline: 2.2842x; 1.1164x over previous
#include <cuda_runtime.h>
#include <cuda_bf16.h>
#include <stdint.h>

#define R_DIM 512
#define S_DIM 256
#define D_DIM 256
#define NROWS (R_DIM * S_DIM)        // 131072

// ---------------- scratch (static device arrays; no cudaMalloc) ------------
__device__ __nv_bfloat16 g_Mn[NROWS * D_DIM];             // layernormed M (bf16)
__device__ __nv_bfloat16 g_QKVG[(size_t)NROWS * 1024];    // q|k|v|gate (bf16)
__device__ __nv_bfloat16 g_O[NROWS * D_DIM];              // gated attn out (bf16)
__device__ __nv_bfloat16 g_Wb[5 * 65536];                 // Wq|Wk|Wv|Wg|Wo (bf16)

// q scale: C^-0.5 * log2(e) — attention uses exp2
#define Q_SCALE_LOG2E 0.2550348658f

// ---------------------------------------------------------------------------
// mma.sync bf16 + cp.async helpers (base PTX target)
// ---------------------------------------------------------------------------
__device__ __forceinline__ void mma_bf16(float* d, const uint32_t* a, const uint32_t* b) {
    asm volatile("mma.sync.aligned.m16n8k16.row.col.f32.bf16.bf16.f32 "
        "{%0,%1,%2,%3}, {%4,%5,%6,%7}, {%8,%9}, {%0,%1,%2,%3};"
        : "+f"(d[0]), "+f"(d[1]), "+f"(d[2]), "+f"(d[3])
        : "r"(a[0]), "r"(a[1]), "r"(a[2]), "r"(a[3]), "r"(b[0]), "r"(b[1]));
}

__device__ __forceinline__ void cp16(const void* sdst, const void* gsrc) {
    uint32_t d = (uint32_t)__cvta_generic_to_shared(sdst);
    asm volatile("cp.async.cg.shared.global [%0], [%1], 16;" :: "r"(d), "l"(gsrc));
}

__device__ __forceinline__ float ex2_approx(float x) {
    float y;
    asm("ex2.approx.ftz.f32 %0, %1;" : "=f"(y) : "f"(x));
    return y;
}

// ---------------------------------------------------------------------------
// Shared-memory geometry for the 128x256 bf16 GEMM tile, K-chunks of 32.
// Row stride 72 bf16 (144 B): fragment loads bank-conflict-free ((4g+tg)%32).
// A: 128x72, B: 256x72 bf16; double-buffered.
// ---------------------------------------------------------------------------
#define GS_STRIDE 72
#define GS_BOFF   9216
#define GS_BUF    27648                 // bf16 elems per buffer
#define GS_BYTES  110592

__device__ __forceinline__ void stage_chunk(const __nv_bfloat16* __restrict__ A,
                                            const __nv_bfloat16* __restrict__ B,
                                            int k0, __nv_bfloat16* buf) {
    int tid = threadIdx.x;
    __nv_bfloat16* sA = buf;
    __nv_bfloat16* sB = buf + GS_BOFF;
#pragma unroll
    for (int i = 0; i < 2; i++) {          // A: 128 rows x 4 slots of 8 bf16
        int slot = tid + i * 256;
        int row = slot >> 2, kq = (slot & 3) * 8;
        cp16(sA + row * GS_STRIDE + kq, A + (size_t)row * 256 + k0 + kq);
    }
#pragma unroll
    for (int i = 0; i < 4; i++) {          // B: 256 rows x 4 slots
        int slot = tid + i * 256;
        int row = slot >> 2, kq = (slot & 3) * 8;
        cp16(sB + row * GS_STRIDE + kq, B + (size_t)row * 256 + k0 + kq);
    }
    asm volatile("cp.async.commit_group;");
}

__device__ __forceinline__ void compute_chunk(const __nv_bfloat16* buf, float acc[4][8][4],
                                              int wm, int wn, int g, int tg) {
    const __nv_bfloat16* As = buf;
    const __nv_bfloat16* Bs = buf + GS_BOFF;
#pragma unroll
    for (int ks = 0; ks < 2; ks++) {       // 2 x K=16 per 32-chunk
        int kc = ks * 16 + 2 * tg;
        uint32_t a[4][4], b[8][2];
#pragma unroll
        for (int mt = 0; mt < 4; mt++) {
            const __nv_bfloat16* p = As + (wm * 64 + mt * 16 + g) * GS_STRIDE + kc;
            a[mt][0] = *(const uint32_t*)(p);
            a[mt][1] = *(const uint32_t*)(p + 8 * GS_STRIDE);
            a[mt][2] = *(const uint32_t*)(p + 8);
            a[mt][3] = *(const uint32_t*)(p + 8 * GS_STRIDE + 8);
        }
#pragma unroll
        for (int nt = 0; nt < 8; nt++) {
            const __nv_bfloat16* p = Bs + (wn * 64 + nt * 8 + g) * GS_STRIDE + kc;
            b[nt][0] = *(const uint32_t*)(p);
            b[nt][1] = *(const uint32_t*)(p + 8);
        }
#pragma unroll
        for (int mt = 0; mt < 4; mt++)
#pragma unroll
            for (int nt = 0; nt < 8; nt++)
                mma_bf16(acc[mt][nt], a[mt], b[nt]);
    }
}

__device__ __forceinline__ void gemm_128x256(const __nv_bfloat16* __restrict__ Abase,
                                             const __nv_bfloat16* __restrict__ Bbase,
                                             float acc[4][8][4]) {
    extern __shared__ __nv_bfloat16 smb[];
    int tid = threadIdx.x, wid = tid >> 5, lane = tid & 31;
    int g = lane >> 2, tg = lane & 3;
    int wm = wid & 1, wn = wid >> 1;

#pragma unroll
    for (int mt = 0; mt < 4; mt++)
#pragma unroll
        for (int nt = 0; nt < 8; nt++)
#pragma unroll
            for (int i = 0; i < 4; i++) acc[mt][nt][i] = 0.f;

    stage_chunk(Abase, Bbase, 0, smb);
    stage_chunk(Abase, Bbase, 32, smb + GS_BUF);

#pragma unroll 1
    for (int c = 0; c < 8; c++) {
        if (c == 7) asm volatile("cp.async.wait_group 0;" ::: "memory");
        else        asm volatile("cp.async.wait_group 1;" ::: "memory");
        __syncthreads();
        compute_chunk(smb + (c & 1) * GS_BUF, acc, wm, wn, g, tg);
        __syncthreads();
        if (c + 2 < 8) stage_chunk(Abase, Bbase, (c + 2) * 32, smb + (c & 1) * GS_BUF);
    }
}

// ---------------------------------------------------------------------------
// Kernel 0: convert the 5 weight matrices fp32 -> bf16.
// ---------------------------------------------------------------------------
__global__ __launch_bounds__(256) void cvt_w(const float* __restrict__ Wq,
                                             const float* __restrict__ Wk,
                                             const float* __restrict__ Wv,
                                             const float* __restrict__ Wg,
                                             const float* __restrict__ Wo) {
    int idx = (blockIdx.x * 256 + threadIdx.x) * 4;
    int mat = idx >> 16, off = idx & 65535;
    const float* src = (mat == 0) ? Wq : (mat == 1) ? Wk : (mat == 2) ? Wv
                     : (mat == 3) ? Wg : Wo;
    float4 v = *(const float4*)(src + off);
    *(__nv_bfloat162*)(g_Wb + idx)     = __floats2bfloat162_rn(v.x, v.y);
    *(__nv_bfloat162*)(g_Wb + idx + 2) = __floats2bfloat162_rn(v.z, v.w);
}

// ---------------------------------------------------------------------------
// Kernel 1: LayerNorm over D=256 with implicit [S,R]->[R,S] transpose; bf16 out.
// ---------------------------------------------------------------------------
__global__ __launch_bounds__(256) void ln_kernel(const float* __restrict__ M_raw,
                                                 const float* __restrict__ lns,
                                                 const float* __restrict__ lnb) {
    int n    = (blockIdx.x * 256 + threadIdx.x) >> 5;
    int lane = threadIdx.x & 31;
    int r = n >> 8;
    int s = n & 255;
    const float* src = M_raw + ((size_t)s * R_DIM + r) * D_DIM;

    float v[8];
#pragma unroll
    for (int i = 0; i < 8; i++) v[i] = src[lane + 32 * i];

    float sum = 0.f;
#pragma unroll
    for (int i = 0; i < 8; i++) sum += v[i];
#pragma unroll
    for (int o = 16; o > 0; o >>= 1) sum += __shfl_xor_sync(0xffffffff, sum, o);
    float mean = sum * (1.0f / 256.0f);

    float var = 0.f;
#pragma unroll
    for (int i = 0; i < 8; i++) { float d = v[i] - mean; var += d * d; }
#pragma unroll
    for (int o = 16; o > 0; o >>= 1) var += __shfl_xor_sync(0xffffffff, var, o);
    var *= (1.0f / 256.0f);
    float inv = rsqrtf(var + 1e-5f);

    __nv_bfloat16* dst = g_Mn + (size_t)n * D_DIM;
#pragma unroll
    for (int i = 0; i < 8; i++) {
        int d = lane + 32 * i;
        dst[d] = __float2bfloat16((v[i] - mean) * inv * lns[d] + lnb[d]);
    }
}

// ---------------------------------------------------------------------------
// Kernel 2: fused QKVG projection via bf16 mma; bf16 output.
// ---------------------------------------------------------------------------
__global__ __launch_bounds__(256) void proj_mma(const float* __restrict__ bg) {
    int mat = blockIdx.x;
    int by  = blockIdx.y;

    float acc[4][8][4];
    gemm_128x256(g_Mn + (size_t)by * 128 * 256, g_Wb + mat * 65536, acc);

    int tid = threadIdx.x, wid = tid >> 5, lane = tid & 31;
    int g = lane >> 2, tg = lane & 3;
    int wm = wid & 1, wn = wid >> 1;
    int row0 = by * 128 + wm * 64;

#pragma unroll
    for (int mt = 0; mt < 4; mt++) {
#pragma unroll
        for (int nt = 0; nt < 8; nt++) {
            int col = wn * 64 + nt * 8 + 2 * tg;
            float v0 = acc[mt][nt][0], v1 = acc[mt][nt][1];
            float v2 = acc[mt][nt][2], v3 = acc[mt][nt][3];
            if (mat == 0) {
                v0 *= Q_SCALE_LOG2E; v1 *= Q_SCALE_LOG2E;
                v2 *= Q_SCALE_LOG2E; v3 *= Q_SCALE_LOG2E;
            } else if (mat == 3) {
                float b0 = bg[col], b1 = bg[col + 1];
                v0 = 1.f / (1.f + __expf(-(v0 + b0)));
                v1 = 1.f / (1.f + __expf(-(v1 + b1)));
                v2 = 1.f / (1.f + __expf(-(v2 + b0)));
                v3 = 1.f / (1.f + __expf(-(v3 + b1)));
            }
            size_t i0 = (size_t)(row0 + mt * 16 + g) * 1024 + mat * 256 + col;
            *(__nv_bfloat162*)(g_QKVG + i0)            = __floats2bfloat162_rn(v0, v1);
            *(__nv_bfloat162*)(g_QKVG + i0 + 8 * 1024) = __floats2bfloat162_rn(v2, v3);
        }
    }
}

// ---------------------------------------------------------------------------
// Kernel 3: tensor-core attention, all-bf16, low-smem for 2 CTAs/SM.
// CTA per (r,h), 8 warps, 32 q rows/warp.
//  - q fragments loaded directly from global (L1-friendly, one-time).
//  - K/V tiles stride 40 bf16 (80 B): frag words (20g+tg)%32 all distinct;
//    V 2B gathers hit 16 words 2-lane-broadcast — conflict-free.
//  - P per-warp tile stride 72 (row len 64), words (4g+tg) distinct.
// SMEM (bf16 elems): Ks@0 (256x40), Vs@10240 (256x40), Ps@20480 + wid*2304.
// Total 38912 elems = 77824 B -> 2 CTAs/SM (regs 118*512 < 64K).
// ---------------------------------------------------------------------------
#define AT_SMEM_BYTES 77824

__global__ __launch_bounds__(256) void attn_mma() {
    extern __shared__ __nv_bfloat16 smb[];
    __nv_bfloat16* Ks = smb;
    __nv_bfloat16* Vs = smb + 10240;

    int tid = threadIdx.x, wid = tid >> 5, lane = tid & 31;
    int g = lane >> 2, tg = lane & 3;
    __nv_bfloat16* Ps = smb + 20480 + wid * 2304;

    int h = blockIdx.x;
    int r = blockIdx.y;
    const __nv_bfloat16* base = g_QKVG + (size_t)r * 256 * 1024 + h * 32;

    // ---- stage k/v tiles via cp.async (stride 40) -------------------------
#pragma unroll
    for (int i = 0; i < 4; i++) {
        int slot = tid + i * 256;              // 1024: 256 rows x 4 slots of 8
        int row = slot >> 2, c8 = (slot & 3) * 8;
        const __nv_bfloat16* gsrc = base + (size_t)row * 1024 + c8;
        cp16(Ks + row * 40 + c8, gsrc + 256);
        cp16(Vs + row * 40 + c8, gsrc + 512);
    }
    asm volatile("cp.async.commit_group;");

    // ---- q fragments straight from global ---------------------------------
    uint32_t qa[2][2][4];
#pragma unroll
    for (int mt = 0; mt < 2; mt++)
#pragma unroll
        for (int ks = 0; ks < 2; ks++) {
            const __nv_bfloat16* p = base + (size_t)(wid * 32 + mt * 16 + g) * 1024
                                          + ks * 16 + 2 * tg;
            qa[mt][ks][0] = *(const uint32_t*)(p);
            qa[mt][ks][1] = *(const uint32_t*)(p + 8 * 1024);
            qa[mt][ks][2] = *(const uint32_t*)(p + 8);
            qa[mt][ks][3] = *(const uint32_t*)(p + 8 * 1024 + 8);
        }

    float acc_o[2][4][4];
#pragma unroll
    for (int mt = 0; mt < 2; mt++)
#pragma unroll
        for (int nt = 0; nt < 4; nt++)
#pragma unroll
            for (int i = 0; i < 4; i++) acc_o[mt][nt][i] = 0.f;
    float lrow[2][2] = {{0.f, 0.f}, {0.f, 0.f}};

    asm volatile("cp.async.wait_group 0;" ::: "memory");
    __syncthreads();

    // ---- main loop over 4 key blocks of 64 --------------------------------
#pragma unroll 1
    for (int jb = 0; jb < 4; jb++) {
        float accl[2][8][4];
#pragma unroll
        for (int mt = 0; mt < 2; mt++)
#pragma unroll
            for (int nt = 0; nt < 8; nt++)
#pragma unroll
                for (int i = 0; i < 4; i++) accl[mt][nt][i] = 0.f;

        // logits: q[32,32] @ K[64,32]^T  (2 k-steps of 16)
#pragma unroll
        for (int ks = 0; ks < 2; ks++) {
            uint32_t b[8][2];
#pragma unroll
            for (int nt = 0; nt < 8; nt++) {
                const __nv_bfloat16* p = Ks + (jb * 64 + nt * 8 + g) * 40 + ks * 16 + 2 * tg;
                b[nt][0] = *(const uint32_t*)(p);
                b[nt][1] = *(const uint32_t*)(p + 8);
            }
#pragma unroll
            for (int mt = 0; mt < 2; mt++)
#pragma unroll
                for (int nt = 0; nt < 8; nt++)
                    mma_bf16(accl[mt][nt], qa[mt][ks], b[nt]);
        }

        // exp2, accumulate l, store P block as bf16 (C-frag -> row-major)
#pragma unroll
        for (int mt = 0; mt < 2; mt++)
#pragma unroll
            for (int nt = 0; nt < 8; nt++) {
                float p0 = ex2_approx(accl[mt][nt][0]);
                float p1 = ex2_approx(accl[mt][nt][1]);
                float p2 = ex2_approx(accl[mt][nt][2]);
                float p3 = ex2_approx(accl[mt][nt][3]);
                lrow[mt][0] += p0 + p1;
                lrow[mt][1] += p2 + p3;
                int col = nt * 8 + 2 * tg;
                *(__nv_bfloat162*)(Ps + (mt * 16 + g) * 72 + col)     = __floats2bfloat162_rn(p0, p1);
                *(__nv_bfloat162*)(Ps + (mt * 16 + g + 8) * 72 + col) = __floats2bfloat162_rn(p2, p3);
            }
        __syncwarp();

        // o += P[32,64] @ V[64,32]  (4 k-steps of 16)
#pragma unroll
        for (int ks = 0; ks < 4; ks++) {
            uint32_t a[2][4], b[4][2];
#pragma unroll
            for (int mt = 0; mt < 2; mt++) {
                const __nv_bfloat16* p = Ps + (mt * 16 + g) * 72 + ks * 16 + 2 * tg;
                a[mt][0] = *(const uint32_t*)(p);
                a[mt][1] = *(const uint32_t*)(p + 8 * 72);
                a[mt][2] = *(const uint32_t*)(p + 8);
                a[mt][3] = *(const uint32_t*)(p + 8 * 72 + 8);
            }
#pragma unroll
            for (int nt = 0; nt < 4; nt++) {
                const unsigned short* vp = (const unsigned short*)
                    (Vs + (jb * 64 + ks * 16 + 2 * tg) * 40 + nt * 8 + g);
                b[nt][0] = (uint32_t)vp[0]      | ((uint32_t)vp[40]     << 16);
                b[nt][1] = (uint32_t)vp[8 * 40] | ((uint32_t)vp[9 * 40] << 16);
            }
#pragma unroll
            for (int mt = 0; mt < 2; mt++)
#pragma unroll
                for (int nt = 0; nt < 4; nt++)
                    mma_bf16(acc_o[mt][nt], a[mt], b[nt]);
        }
        __syncwarp();
    }

    // ---- reduce l across the tg quad --------------------------------------
#pragma unroll
    for (int mt = 0; mt < 2; mt++)
#pragma unroll
        for (int hh = 0; hh < 2; hh++) {
            float l = lrow[mt][hh];
            l += __shfl_xor_sync(0xffffffff, l, 1);
            l += __shfl_xor_sync(0xffffffff, l, 2);
            lrow[mt][hh] = 1.0f / l;
        }

    // ---- normalize, gate, store bf16 --------------------------------------
#pragma unroll
    for (int mt = 0; mt < 2; mt++) {
        int row_lo = wid * 32 + mt * 16 + g;
        int row_hi = row_lo + 8;
#pragma unroll
        for (int nt = 0; nt < 4; nt++) {
            int col = nt * 8 + 2 * tg;
            float2 g0 = __bfloat1622float2(
                *(const __nv_bfloat162*)(base + (size_t)row_lo * 1024 + 768 + col));
            float2 g1 = __bfloat1622float2(
                *(const __nv_bfloat162*)(base + (size_t)row_hi * 1024 + 768 + col));
            float o0x = acc_o[mt][nt][0] * lrow[mt][0] * g0.x;
            float o0y = acc_o[mt][nt][1] * lrow[mt][0] * g0.y;
            float o1x = acc_o[mt][nt][2] * lrow[mt][1] * g1.x;
            float o1y = acc_o[mt][nt][3] * lrow[mt][1] * g1.y;
            size_t i0 = ((size_t)(r * 256 + row_lo)) * 256 + h * 32 + col;
            size_t i1 = ((size_t)(r * 256 + row_hi)) * 256 + h * 32 + col;
            *(__nv_bfloat162*)(g_O + i0) = __floats2bfloat162_rn(o0x, o0y);
            *(__nv_bfloat162*)(g_O + i1) = __floats2bfloat162_rn(o1x, o1y);
        }
    }
}

// ---------------------------------------------------------------------------
// Kernel 4: output projection (bf16 mma) + bias + residual + transpose.
// ---------------------------------------------------------------------------
__global__ __launch_bounds__(256) void out_mma(const float* __restrict__ bo,
                                               const float* __restrict__ M_raw,
                                               float* __restrict__ out) {
    int by = blockIdx.x;

    float acc[4][8][4];
    gemm_128x256(g_O + (size_t)by * 128 * 256, g_Wb + 4 * 65536, acc);

    int tid = threadIdx.x, wid = tid >> 5, lane = tid & 31;
    int g = lane >> 2, tg = lane & 3;
    int wm = wid & 1, wn = wid >> 1;
    int row0 = by * 128 + wm * 64;

#pragma unroll
    for (int mt = 0; mt < 4; mt++) {
        int n0 = row0 + mt * 16 + g;
        int rr = n0 >> 8, ss = n0 & 255;
#pragma unroll
        for (int nt = 0; nt < 8; nt++) {
            int d = wn * 64 + nt * 8 + 2 * tg;
            float b0 = bo[d], b1 = bo[d + 1];
            size_t i0 = ((size_t)ss * R_DIM + rr) * D_DIM + d;
            size_t i1 = ((size_t)(ss + 8) * R_DIM + rr) * D_DIM + d;
            float2 m0 = *(const float2*)(M_raw + i0);
            float2 m1 = *(const float2*)(M_raw + i1);
            *(float2*)(out + i0) = make_float2(acc[mt][nt][0] + b0 + m0.x,
                                               acc[mt][nt][1] + b1 + m0.y);
            *(float2*)(out + i1) = make_float2(acc[mt][nt][2] + b0 + m1.x,
                                               acc[mt][nt][3] + b1 + m1.y);
        }
    }
}

// ---------------------------------------------------------------------------
extern "C" void kernel_launch(void* const* d_in, const int* in_sizes, int n_in,
                              void* d_out, int out_size) {
    const float* M_raw = (const float*)d_in[0];
    const float* lns   = (const float*)d_in[1];
    const float* lnb   = (const float*)d_in[2];
    const float* Wq    = (const float*)d_in[3];
    const float* Wk    = (const float*)d_in[4];
    const float* Wv    = (const float*)d_in[5];
    const float* Wg    = (const float*)d_in[6];
    const float* bg    = (const float*)d_in[7];
    const float* Wo    = (const float*)d_in[8];
    const float* bo    = (const float*)d_in[9];
    float* out = (float*)d_out;

    cudaFuncSetAttribute(proj_mma, cudaFuncAttributeMaxDynamicSharedMemorySize, GS_BYTES);
    cudaFuncSetAttribute(out_mma,  cudaFuncAttributeMaxDynamicSharedMemorySize, GS_BYTES);
    cudaFuncSetAttribute(attn_mma, cudaFuncAttributeMaxDynamicSharedMemorySize, AT_SMEM_BYTES);

    cvt_w<<<320, 256>>>(Wq, Wk, Wv, Wg, Wo);

    ln_kernel<<<NROWS / 8, 256>>>(M_raw, lns, lnb);

    dim3 gp(4, NROWS / 128);
    proj_mma<<<gp, 256, GS_BYTES>>>(bg);

    dim3 ga(8, R_DIM);
    attn_mma<<<ga, 256, AT_SMEM_BYTES>>>();

    out_mma<<<NROWS / 128, 256, GS_BYTES>>>(bo, M_raw, out);
}